// round 5
// baseline (speedup 1.0000x reference)
#include <cuda_runtime.h>
#include <cuda_bf16.h>

#define EPS 0.01f

__device__ float g_acc = 0.0f;          // reset by last block each run
__device__ unsigned int g_count = 0;    // reset by last block each run

__global__ void __launch_bounds__(256, 4)   // cap regs at 64, 4 CTAs/SM
elc_fused_kernel(const float4* __restrict__ pred4,
                 const int4*   __restrict__ label4,
                 const float*  __restrict__ Wl,
                 const float*  __restrict__ label_sum,
                 const float4* __restrict__ em4,
                 int n4, int n_ls,
                 float* __restrict__ out)
{
    __shared__ float sWl[16];
    if (threadIdx.x < 16) sWl[threadIdx.x] = Wl[threadIdx.x];
    __syncthreads();

    float acc = 0.0f;
    const int stride = gridDim.x * blockDim.x;
    int i = blockIdx.x * blockDim.x + threadIdx.x;

    // 4x strided unroll: issue all 12 LDG.128 before consuming any result.
    // With the 64-reg budget ptxas can keep them all in flight (MLP=12/thread).
    for (; i + 3 * stride < n4; i += 4 * stride) {
        const int j0 = i, j1 = i + stride, j2 = i + 2 * stride, j3 = i + 3 * stride;

        float4 p0 = pred4[j0];
        float4 p1 = pred4[j1];
        float4 p2 = pred4[j2];
        float4 p3 = pred4[j3];
        int4   l0 = label4[j0];
        int4   l1 = label4[j1];
        int4   l2 = label4[j2];
        int4   l3 = label4[j3];
        float4 e0 = em4[j0];
        float4 e1 = em4[j1];
        float4 e2 = em4[j2];
        float4 e3 = em4[j3];

        const float w0 = sWl[(j0 >> 16) & 15];
        const float w1 = sWl[(j1 >> 16) & 15];
        const float w2 = sWl[(j2 >> 16) & 15];
        const float w3 = sWl[(j3 >> 16) & 15];

        float t0 = 0.0f, t1 = 0.0f, t2 = 0.0f, t3 = 0.0f;
        if (l0.x == 1) t0 += __logf(p0.x + EPS) * e0.x;
        if (l0.y == 1) t0 += __logf(p0.y + EPS) * e0.y;
        if (l0.z == 1) t0 += __logf(p0.z + EPS) * e0.z;
        if (l0.w == 1) t0 += __logf(p0.w + EPS) * e0.w;
        if (l1.x == 1) t1 += __logf(p1.x + EPS) * e1.x;
        if (l1.y == 1) t1 += __logf(p1.y + EPS) * e1.y;
        if (l1.z == 1) t1 += __logf(p1.z + EPS) * e1.z;
        if (l1.w == 1) t1 += __logf(p1.w + EPS) * e1.w;
        if (l2.x == 1) t2 += __logf(p2.x + EPS) * e2.x;
        if (l2.y == 1) t2 += __logf(p2.y + EPS) * e2.y;
        if (l2.z == 1) t2 += __logf(p2.z + EPS) * e2.z;
        if (l2.w == 1) t2 += __logf(p2.w + EPS) * e2.w;
        if (l3.x == 1) t3 += __logf(p3.x + EPS) * e3.x;
        if (l3.y == 1) t3 += __logf(p3.y + EPS) * e3.y;
        if (l3.z == 1) t3 += __logf(p3.z + EPS) * e3.z;
        if (l3.w == 1) t3 += __logf(p3.w + EPS) * e3.w;

        acc = fmaf(-w0, t0, acc);
        acc = fmaf(-w1, t1, acc);
        acc = fmaf(-w2, t2, acc);
        acc = fmaf(-w3, t3, acc);
    }
    // remainder (up to 3 strided positions)
    for (; i < n4; i += stride) {
        float4 p = pred4[i];
        int4   l = label4[i];
        float4 e = em4[i];
        const float w = sWl[(i >> 16) & 15];
        float t = 0.0f;
        if (l.x == 1) t += __logf(p.x + EPS) * e.x;
        if (l.y == 1) t += __logf(p.y + EPS) * e.y;
        if (l.z == 1) t += __logf(p.z + EPS) * e.z;
        if (l.w == 1) t += __logf(p.w + EPS) * e.w;
        acc = fmaf(-w, t, acc);
    }

    // block reduce
    #pragma unroll
    for (int o = 16; o > 0; o >>= 1)
        acc += __shfl_xor_sync(0xffffffff, acc, o);

    __shared__ float red[8];
    const int lane = threadIdx.x & 31;
    const int wid  = threadIdx.x >> 5;
    if (lane == 0) red[wid] = acc;
    __syncthreads();
    if (wid == 0) {
        acc = (lane < (blockDim.x >> 5)) ? red[lane] : 0.0f;
        #pragma unroll
        for (int o = 4; o > 0; o >>= 1)
            acc += __shfl_xor_sync(0xffffffff, acc, o);
        if (lane == 0) atomicAdd(&g_acc, acc);   // device-scope atomic
    }
    __syncthreads();

    // arrival: ONE release-atomic per block (thread 0).
    __shared__ bool s_last;
    if (threadIdx.x == 0) {
        unsigned int old;
        asm volatile("atom.acq_rel.gpu.global.add.u32 %0, [%1], %2;"
                     : "=r"(old) : "l"(&g_count), "r"(1u) : "memory");
        s_last = (old == gridDim.x - 1);
    }
    __syncthreads();
    if (!s_last) return;

    if (threadIdx.x == 0) {
        float tot;
        asm volatile("ld.acquire.gpu.global.f32 %0, [%1];"
                     : "=f"(tot) : "l"(&g_acc) : "memory");
        float s = 0.0f;
        for (int k = 0; k < n_ls; ++k) s += label_sum[k];
        out[0] = tot / s;
        g_acc   = 0.0f;   // reset for next graph replay (deterministic)
        g_count = 0u;
    }
}

extern "C" void kernel_launch(void* const* d_in, const int* in_sizes, int n_in,
                              void* d_out, int out_size)
{
    // metadata order: pred(f32), label(i32), Wl(f32[16]), label_sum(f32[16]), existmap(f32)
    const float* pred      = (const float*)d_in[0];
    const int*   label     = (const int*)  d_in[1];
    const float* Wl        = (const float*)d_in[2];
    const float* label_sum = (const float*)d_in[3];
    const float* em        = (const float*)d_in[4];
    float* out = (float*)d_out;

    const int n_total = in_sizes[0];
    const int n4 = n_total >> 2;   // 33.55M elems, divisible by 4

    const int threads = 256;
    int blocks = 592;  // 4 CTAs/SM * 148 SMs (64-reg budget per thread)
    int max_blocks = (n4 + threads - 1) / threads;
    if (blocks > max_blocks) blocks = max_blocks;
    if (blocks < 1) blocks = 1;

    elc_fused_kernel<<<blocks, threads>>>(
        (const float4*)pred, (const int4*)label, Wl, label_sum,
        (const float4*)em, n4, in_sizes[3], out);
}